// round 1
// baseline (speedup 1.0000x reference)
#include <cuda_runtime.h>
#include <math.h>

#define NNODES 49152
#define NEDGES 196608
#define NGRAPH 1024
#define SNODES 48
#define DFEAT  256
#define GD     512

// ---------------- scratch (static __device__: no allocations allowed) ----------------
__device__ float g_A [(size_t)NNODES * 1024];   // [mean1 | x | lap]  (cols 0:512 mean1, 512:768 x, 768:1024 lap)
__device__ float g_h [(size_t)NNODES * GD];     // conv1 output (post-GELU)
__device__ float g_m2[(size_t)NNODES * GD];     // conv2 per-node mean aggregation
__device__ float g_A2[(size_t)NGRAPH * 1024];   // [pool(mean2) | pool(h)]
__device__ int   g_deg [NNODES];
__device__ int   g_cnt [NNODES];
__device__ int   g_roff[NNODES + 1];
__device__ int   g_coff[NNODES + 1];
__device__ int   g_curr[NNODES];
__device__ int   g_curc[NNODES];
__device__ int   g_rnbr[NEDGES];
__device__ int   g_cnbr[NEDGES];
__device__ float g_rw  [NEDGES];
__device__ float g_dinv[NNODES];
__device__ int   g_is64;

// ---------------- small helpers ----------------
static __device__ __forceinline__ float4 f4z() { return make_float4(0.f, 0.f, 0.f, 0.f); }
static __device__ __forceinline__ float4 f4add(float4 a, float4 b) {
    a.x += b.x; a.y += b.y; a.z += b.z; a.w += b.w; return a;
}
static __device__ __forceinline__ float4 f4fma(float4 a, float w, float4 b) {
    a.x = fmaf(w, b.x, a.x); a.y = fmaf(w, b.y, a.y);
    a.z = fmaf(w, b.z, a.z); a.w = fmaf(w, b.w, a.w); return a;
}
static __device__ __forceinline__ float4 f4scale(float4 a, float s) {
    a.x *= s; a.y *= s; a.z *= s; a.w *= s; return a;
}

// edge accessor: works for int64 or int32 edge_index (device-side dtype flag)
static __device__ __forceinline__ int edge_at(const int* __restrict__ w, int idx) {
    return g_is64 ? w[2 * idx] : w[idx];
}

// ---------------- CSR build ----------------
__global__ void init_kernel(int* deg, int* cnt, int* curr, int* curc) {
    int i = blockIdx.x * blockDim.x + threadIdx.x;
    if (i < NNODES) { deg[i] = 0; cnt[i] = 0; curr[i] = 0; curc[i] = 0; }
    if (i == 0) g_is64 = 1;
}

// int64 (LE) => all odd 32-bit words of the value stream are 0. Any nonzero odd word => int32.
__global__ void detect_kernel(const int* __restrict__ w, int twoE) {
    int i = blockIdx.x * blockDim.x + threadIdx.x;
    if (i < twoE && (i & 1) && w[i] != 0) g_is64 = 0;
}

__global__ void hist_kernel(const int* __restrict__ ew, int E, int* deg, int* cnt) {
    int e = blockIdx.x * blockDim.x + threadIdx.x;
    if (e >= E) return;
    atomicAdd(&deg[edge_at(ew, e)], 1);
    atomicAdd(&cnt[edge_at(ew, E + e)], 1);
}

__global__ void scan_kernel(const int* __restrict__ in, int* __restrict__ out, int n) {
    __shared__ int wsums[32];
    __shared__ int carry;
    int tid = threadIdx.x, lane = tid & 31, wid = tid >> 5;
    if (tid == 0) carry = 0;
    __syncthreads();
    for (int base = 0; base < n; base += 1024) {
        int i = base + tid;
        int v = (i < n) ? in[i] : 0;
        int x = v;
        #pragma unroll
        for (int off = 1; off < 32; off <<= 1) {
            int y = __shfl_up_sync(0xffffffffu, x, off);
            if (lane >= off) x += y;
        }
        if (lane == 31) wsums[wid] = x;
        __syncthreads();
        if (wid == 0) {
            int s = wsums[lane];
            #pragma unroll
            for (int off = 1; off < 32; off <<= 1) {
                int y = __shfl_up_sync(0xffffffffu, s, off);
                if (lane >= off) s += y;
            }
            wsums[lane] = s;
        }
        __syncthreads();
        int excl = carry + (wid ? wsums[wid - 1] : 0) + x - v;
        if (i < n) out[i] = excl;
        __syncthreads();
        if (tid == 0) carry += wsums[31];
        __syncthreads();
    }
    if (tid == 0) out[n] = carry;
}

__global__ void dinv_kernel(const int* __restrict__ deg, float* __restrict__ dinv) {
    int i = blockIdx.x * blockDim.x + threadIdx.x;
    if (i < NNODES) {
        int d = deg[i];
        dinv[i] = (d > 0) ? rsqrtf((float)d) : 0.f;
    }
}

__global__ void fill_kernel(const int* __restrict__ ew, int E,
                            const float* __restrict__ dinv,
                            const int* __restrict__ roff, const int* __restrict__ coff,
                            int* curr, int* curc,
                            int* __restrict__ rnbr, float* __restrict__ rw,
                            int* __restrict__ cnbr) {
    int e = blockIdx.x * blockDim.x + threadIdx.x;
    if (e >= E) return;
    int r = edge_at(ew, e);
    int c = edge_at(ew, E + e);
    float w = -(dinv[r] * dinv[c]);
    int p = roff[r] + atomicAdd(&curr[r], 1);
    rnbr[p] = c; rw[p] = w;
    int q = coff[c] + atomicAdd(&curc[c], 1);
    cnbr[q] = r;
}

// ---------------- lap + concat: A[i, 512:768]=x_i, A[i, 768:1024]=x_i + sum_e w_e x[col_e] ----------------
__global__ void lap_kernel(const float* __restrict__ x,
                           const int* __restrict__ roff,
                           const int* __restrict__ rnbr,
                           const float* __restrict__ rw,
                           float* __restrict__ A) {
    int gw   = (blockIdx.x * blockDim.x + threadIdx.x) >> 5;
    int lane = threadIdx.x & 31;
    if (gw >= NNODES) return;
    const float4* xi = (const float4*)(x + (size_t)gw * DFEAT);
    float4 a0 = xi[lane], a1 = xi[lane + 32];
    float4 s0 = a0, s1 = a1;
    int e = roff[gw], end = roff[gw + 1];
    for (; e < end; ++e) {
        int   c = rnbr[e];
        float w = rw[e];
        const float4* xc = (const float4*)(x + (size_t)c * DFEAT);
        s0 = f4fma(s0, w, xc[lane]);
        s1 = f4fma(s1, w, xc[lane + 32]);
    }
    float4* Af = (float4*)(A + (size_t)gw * 1024);
    Af[128 + lane] = a0; Af[160 + lane] = a1;   // x       -> cols 512:768
    Af[192 + lane] = s0; Af[224 + lane] = s1;   // lap_x   -> cols 768:1024
}

// ---------------- mean aggregation (gather via col-CSR): dst[i] = (sum_{src in N(i)} feat[src]) / max(cnt,1) ----------------
__global__ void agg_kernel(const float* __restrict__ src, int sstride,
                           float* __restrict__ dst, int dstride,
                           const int* __restrict__ coff, const int* __restrict__ cnbr) {
    int gw   = (blockIdx.x * blockDim.x + threadIdx.x) >> 5;
    int lane = threadIdx.x & 31;
    if (gw >= NNODES) return;
    float4 a0 = f4z(), a1 = f4z(), a2 = f4z(), a3 = f4z();
    int beg = coff[gw], end = coff[gw + 1];
    for (int e = beg; e < end; ++e) {
        const float4* p = (const float4*)(src + (size_t)cnbr[e] * sstride);
        a0 = f4add(a0, p[lane]);
        a1 = f4add(a1, p[lane + 32]);
        a2 = f4add(a2, p[lane + 64]);
        a3 = f4add(a3, p[lane + 96]);
    }
    int cnt = end - beg;
    float sc = 1.f / (float)(cnt > 0 ? cnt : 1);
    float4* q = (float4*)(dst + (size_t)gw * dstride);
    q[lane]      = f4scale(a0, sc);
    q[lane + 32] = f4scale(a1, sc);
    q[lane + 64] = f4scale(a2, sc);
    q[lane + 96] = f4scale(a3, sc);
}

// ---------------- fp32 GEMM: C[M,512] = A[M,1024] @ [Wl | Wr]^T + bias, optional exact GELU ----------------
template <bool GELU>
__global__ void __launch_bounds__(256, 2) gemm_kernel(
    const float* __restrict__ A,
    const float* __restrict__ Wl, const float* __restrict__ Wr,
    const float* __restrict__ bias,
    float* __restrict__ C) {
    __shared__ float As[8][132];
    __shared__ float Bs[8][132];
    int tid = threadIdx.x;
    int tx = tid & 15, ty = tid >> 4;
    int bm = blockIdx.y * 128, bn = blockIdx.x * 128;
    int lrow = tid >> 1;
    int lk   = (tid & 1) * 4;

    float acc[8][8];
    #pragma unroll
    for (int i = 0; i < 8; ++i)
        #pragma unroll
        for (int j = 0; j < 8; ++j) acc[i][j] = 0.f;

    const float* Aptr = A + (size_t)(bm + lrow) * 1024 + lk;

    for (int k0 = 0; k0 < 1024; k0 += 8) {
        float4 av = *(const float4*)(Aptr + k0);
        const float* Wp = (k0 < 512) ? Wl : Wr;
        int kk = ((k0 < 512) ? k0 : (k0 - 512)) + lk;
        float4 bv = *(const float4*)(Wp + (size_t)(bn + lrow) * 512 + kk);
        __syncthreads();
        As[lk + 0][lrow] = av.x; As[lk + 1][lrow] = av.y;
        As[lk + 2][lrow] = av.z; As[lk + 3][lrow] = av.w;
        Bs[lk + 0][lrow] = bv.x; Bs[lk + 1][lrow] = bv.y;
        Bs[lk + 2][lrow] = bv.z; Bs[lk + 3][lrow] = bv.w;
        __syncthreads();
        #pragma unroll
        for (int k = 0; k < 8; ++k) {
            float4 a0 = *(const float4*)&As[k][ty * 8];
            float4 a1 = *(const float4*)&As[k][ty * 8 + 4];
            float4 b0 = *(const float4*)&Bs[k][tx * 8];
            float4 b1 = *(const float4*)&Bs[k][tx * 8 + 4];
            float a[8] = {a0.x, a0.y, a0.z, a0.w, a1.x, a1.y, a1.z, a1.w};
            float b[8] = {b0.x, b0.y, b0.z, b0.w, b1.x, b1.y, b1.z, b1.w};
            #pragma unroll
            for (int i = 0; i < 8; ++i)
                #pragma unroll
                for (int j = 0; j < 8; ++j)
                    acc[i][j] = fmaf(a[i], b[j], acc[i][j]);
        }
    }

    #pragma unroll
    for (int i = 0; i < 8; ++i) {
        int m = bm + ty * 8 + i;
        #pragma unroll
        for (int j = 0; j < 8; ++j) {
            int n = bn + tx * 8 + j;
            float v = acc[i][j] + bias[n];
            if (GELU) v = 0.5f * v * (1.0f + erff(v * 0.70710678118654752f));
            C[(size_t)m * GD + n] = v;
        }
    }
}

// ---------------- pool: A2[g] = [ mean_s m2 , mean_s h ] ----------------
__global__ void pool_kernel(const float* __restrict__ m2, const float* __restrict__ h,
                            float* __restrict__ A2) {
    int g = blockIdx.x;
    int t = threadIdx.x;
    int c = t * 2;
    float2 sm = make_float2(0.f, 0.f), sh = make_float2(0.f, 0.f);
    const float* pm = m2 + (size_t)g * SNODES * GD + c;
    const float* ph = h  + (size_t)g * SNODES * GD + c;
    for (int s = 0; s < SNODES; ++s) {
        float2 vm = *(const float2*)(pm + (size_t)s * GD);
        float2 vh = *(const float2*)(ph + (size_t)s * GD);
        sm.x += vm.x; sm.y += vm.y;
        sh.x += vh.x; sh.y += vh.y;
    }
    const float inv = 1.0f / (float)SNODES;
    *(float2*)(A2 + (size_t)g * 1024 + c)       = make_float2(sm.x * inv, sm.y * inv);
    *(float2*)(A2 + (size_t)g * 1024 + 512 + c) = make_float2(sh.x * inv, sh.y * inv);
}

// ---------------- launcher ----------------
extern "C" void kernel_launch(void* const* d_in, const int* in_sizes, int n_in,
                              void* d_out, int out_size) {
    const float* x   = (const float*)d_in[0];
    const int*   ew  = (const int*)  d_in[1];   // raw 32-bit word view of edge_index
    const float* Wl1 = (const float*)d_in[2];
    const float* Wr1 = (const float*)d_in[3];
    const float* b1  = (const float*)d_in[4];
    const float* Wl2 = (const float*)d_in[5];
    const float* Wr2 = (const float*)d_in[6];
    const float* b2  = (const float*)d_in[7];
    int E = in_sizes[1] / 2;

    float *A, *h, *m2, *A2, *rw, *dinv;
    int *deg, *cnt, *roff, *coff, *curr, *curc, *rnbr, *cnbr;
    cudaGetSymbolAddress((void**)&A,    g_A);
    cudaGetSymbolAddress((void**)&h,    g_h);
    cudaGetSymbolAddress((void**)&m2,   g_m2);
    cudaGetSymbolAddress((void**)&A2,   g_A2);
    cudaGetSymbolAddress((void**)&rw,   g_rw);
    cudaGetSymbolAddress((void**)&dinv, g_dinv);
    cudaGetSymbolAddress((void**)&deg,  g_deg);
    cudaGetSymbolAddress((void**)&cnt,  g_cnt);
    cudaGetSymbolAddress((void**)&roff, g_roff);
    cudaGetSymbolAddress((void**)&coff, g_coff);
    cudaGetSymbolAddress((void**)&curr, g_curr);
    cudaGetSymbolAddress((void**)&curc, g_curc);
    cudaGetSymbolAddress((void**)&rnbr, g_rnbr);
    cudaGetSymbolAddress((void**)&cnbr, g_cnbr);

    int eb = (E + 255) / 256;

    init_kernel<<<(NNODES + 255) / 256, 256>>>(deg, cnt, curr, curc);
    detect_kernel<<<(2 * E + 255) / 256, 256>>>(ew, 2 * E);
    hist_kernel<<<eb, 256>>>(ew, E, deg, cnt);
    scan_kernel<<<1, 1024>>>(deg, roff, NNODES);
    scan_kernel<<<1, 1024>>>(cnt, coff, NNODES);
    dinv_kernel<<<(NNODES + 255) / 256, 256>>>(deg, dinv);
    fill_kernel<<<eb, 256>>>(ew, E, dinv, roff, coff, curr, curc, rnbr, rw, cnbr);

    // lap + concat -> A[:,512:1024]
    lap_kernel<<<NNODES / 8, 256>>>(x, roff, rnbr, rw, A);
    // conv1 mean aggregation of x_comb -> A[:,0:512]
    agg_kernel<<<NNODES / 8, 256>>>(A + 512, 1024, A, 1024, coff, cnbr);
    // conv1 GEMM + bias + exact GELU -> h
    gemm_kernel<true><<<dim3(4, NNODES / 128), 256>>>(A, Wl1, Wr1, b1, h);
    // conv2 mean aggregation of h -> m2
    agg_kernel<<<NNODES / 8, 256>>>(h, GD, m2, GD, coff, cnbr);
    // pool (linear, so pool BEFORE conv2 GEMM): A2 = [pool(m2) | pool(h)]
    pool_kernel<<<NGRAPH, 256>>>(m2, h, A2);
    // conv2 GEMM + bias -> out [1024, 512]
    gemm_kernel<false><<<dim3(4, NGRAPH / 128), 256>>>(A2, Wl2, Wr2, b2, (float*)d_out);
}

// round 2
// speedup vs baseline: 2.0024x; 2.0024x over previous
#include <cuda_runtime.h>
#include <cuda_bf16.h>
#include <math.h>

#define NNODES 49152
#define NEDGES 196608
#define NGRAPH 1024
#define SNODES 48
#define DFEAT  256
#define GD     512
#define NBLK   192      // NNODES / 256

// ---------------- scratch (static __device__: no allocations allowed) ----------------
__device__ float g_A [(size_t)NNODES * 1024];   // [mean1 | x | lap]
__device__ float g_h [(size_t)NNODES * GD];     // conv1 output (post-GELU)
__device__ float g_m2[(size_t)NNODES * GD];     // conv2 per-node mean aggregation
__device__ float g_A2[(size_t)NGRAPH * 1024];   // [pool(mean2) | pool(h)]
__device__ int   g_deg [NNODES];
__device__ int   g_cnt [NNODES];
__device__ int   g_roff[NNODES + 1];
__device__ int   g_coff[NNODES + 1];
__device__ int   g_curr[NNODES];
__device__ int   g_curc[NNODES];
__device__ int   g_rnbr[NEDGES];
__device__ int   g_cnbr[NEDGES];
__device__ float g_rw  [NEDGES];
__device__ float g_dinv[NNODES];
__device__ int   g_bsum[2 * (NBLK + 1)];
__device__ int   g_is64;

// ---------------- small helpers ----------------
static __device__ __forceinline__ float4 f4z() { return make_float4(0.f, 0.f, 0.f, 0.f); }
static __device__ __forceinline__ float4 f4add(float4 a, float4 b) {
    a.x += b.x; a.y += b.y; a.z += b.z; a.w += b.w; return a;
}
static __device__ __forceinline__ float4 f4fma(float4 a, float w, float4 b) {
    a.x = fmaf(w, b.x, a.x); a.y = fmaf(w, b.y, a.y);
    a.z = fmaf(w, b.z, a.z); a.w = fmaf(w, b.w, a.w); return a;
}
static __device__ __forceinline__ float4 f4scale(float4 a, float s) {
    a.x *= s; a.y *= s; a.z *= s; a.w *= s; return a;
}

static __device__ __forceinline__ int edge_at(const int* __restrict__ w, int idx) {
    return g_is64 ? w[2 * idx] : w[idx];
}

// pack two floats into bf16x2 hi, and the bf16x2 of the residuals into lo
static __device__ __forceinline__ unsigned pack_hi_lo(float x, float y, unsigned& lo) {
    __nv_bfloat16 hx = __float2bfloat16(x);
    __nv_bfloat16 hy = __float2bfloat16(y);
    float rx = x - __bfloat162float(hx);
    float ry = y - __bfloat162float(hy);
    __nv_bfloat16 lx = __float2bfloat16(rx);
    __nv_bfloat16 ly = __float2bfloat16(ry);
    lo = (unsigned)__bfloat16_as_ushort(lx) | ((unsigned)__bfloat16_as_ushort(ly) << 16);
    return (unsigned)__bfloat16_as_ushort(hx) | ((unsigned)__bfloat16_as_ushort(hy) << 16);
}

#define MMA_BF16(c, a0, a1, a2, a3, b0, b1)                                           \
    asm volatile(                                                                      \
        "mma.sync.aligned.m16n8k16.row.col.f32.bf16.bf16.f32 "                         \
        "{%0,%1,%2,%3},{%4,%5,%6,%7},{%8,%9},{%0,%1,%2,%3};"                           \
        : "+f"((c)[0]), "+f"((c)[1]), "+f"((c)[2]), "+f"((c)[3])                       \
        : "r"(a0), "r"(a1), "r"(a2), "r"(a3), "r"(b0), "r"(b1))

// ---------------- CSR build ----------------
__global__ void init_kernel(int* deg, int* cnt, int* curr, int* curc) {
    int i = blockIdx.x * blockDim.x + threadIdx.x;
    if (i < NNODES) { deg[i] = 0; cnt[i] = 0; curr[i] = 0; curc[i] = 0; }
    if (i == 0) g_is64 = 1;
}

__global__ void detect_kernel(const int* __restrict__ w, int twoE) {
    int i = blockIdx.x * blockDim.x + threadIdx.x;
    if (i < twoE && (i & 1) && w[i] != 0) g_is64 = 0;
}

__global__ void hist_kernel(const int* __restrict__ ew, int E, int* deg, int* cnt) {
    int e = blockIdx.x * blockDim.x + threadIdx.x;
    if (e >= E) return;
    atomicAdd(&deg[edge_at(ew, e)], 1);
    atomicAdd(&cnt[edge_at(ew, E + e)], 1);
}

// block-wide exclusive scan over 256 threads
static __device__ __forceinline__ int block_excl_scan256(int v) {
    __shared__ int ws[8];
    int lane = threadIdx.x & 31, wid = threadIdx.x >> 5;
    int x = v;
    #pragma unroll
    for (int o = 1; o < 32; o <<= 1) {
        int y = __shfl_up_sync(0xffffffffu, x, o);
        if (lane >= o) x += y;
    }
    if (lane == 31) ws[wid] = x;
    __syncthreads();
    if (threadIdx.x == 0) {
        int s = 0;
        #pragma unroll
        for (int w = 0; w < 8; ++w) { int t = ws[w]; ws[w] = s; s += t; }
    }
    __syncthreads();
    int r = x - v + ws[wid];
    __syncthreads();
    return r;
}

__global__ void scan_p1(const int* __restrict__ deg, const int* __restrict__ cnt,
                        int* __restrict__ bsum) {
    const int* in = blockIdx.y ? cnt : deg;
    int v = in[blockIdx.x * 256 + threadIdx.x];
    __shared__ int ws[8];
    int lane = threadIdx.x & 31, wid = threadIdx.x >> 5;
    #pragma unroll
    for (int o = 16; o > 0; o >>= 1) v += __shfl_down_sync(0xffffffffu, v, o);
    if (lane == 0) ws[wid] = v;
    __syncthreads();
    if (threadIdx.x == 0) {
        int s = 0;
        #pragma unroll
        for (int w = 0; w < 8; ++w) s += ws[w];
        bsum[blockIdx.y * (NBLK + 1) + blockIdx.x] = s;
    }
}

__global__ void scan_p2(int* __restrict__ bsum) {
    #pragma unroll 1
    for (int row = 0; row < 2; ++row) {
        int t = threadIdx.x;
        int v = (t < NBLK) ? bsum[row * (NBLK + 1) + t] : 0;
        int e = block_excl_scan256(v);
        if (t < NBLK) bsum[row * (NBLK + 1) + t] = e;
        if (t == NBLK - 1) bsum[row * (NBLK + 1) + NBLK] = e + v;
        __syncthreads();
    }
}

__global__ void scan_p3(const int* __restrict__ deg, const int* __restrict__ cnt,
                        const int* __restrict__ bsum,
                        int* __restrict__ roff, int* __restrict__ coff) {
    const int* in = blockIdx.y ? cnt : deg;
    int* out = blockIdx.y ? coff : roff;
    int i = blockIdx.x * 256 + threadIdx.x;
    int v = in[i];
    int e = block_excl_scan256(v) + bsum[blockIdx.y * (NBLK + 1) + blockIdx.x];
    out[i] = e;
    if (i == NNODES - 1) out[NNODES] = bsum[blockIdx.y * (NBLK + 1) + NBLK];
}

__global__ void dinv_kernel(const int* __restrict__ deg, float* __restrict__ dinv) {
    int i = blockIdx.x * blockDim.x + threadIdx.x;
    if (i < NNODES) {
        int d = deg[i];
        dinv[i] = (d > 0) ? rsqrtf((float)d) : 0.f;
    }
}

__global__ void fill_kernel(const int* __restrict__ ew, int E,
                            const float* __restrict__ dinv,
                            const int* __restrict__ roff, const int* __restrict__ coff,
                            int* curr, int* curc,
                            int* __restrict__ rnbr, float* __restrict__ rw,
                            int* __restrict__ cnbr) {
    int e = blockIdx.x * blockDim.x + threadIdx.x;
    if (e >= E) return;
    int r = edge_at(ew, e);
    int c = edge_at(ew, E + e);
    float w = -(dinv[r] * dinv[c]);
    int p = roff[r] + atomicAdd(&curr[r], 1);
    rnbr[p] = c; rw[p] = w;
    int q = coff[c] + atomicAdd(&curc[c], 1);
    cnbr[q] = r;
}

// ---------------- lap + concat ----------------
__global__ void lap_kernel(const float* __restrict__ x,
                           const int* __restrict__ roff,
                           const int* __restrict__ rnbr,
                           const float* __restrict__ rw,
                           float* __restrict__ A) {
    int gw   = (blockIdx.x * blockDim.x + threadIdx.x) >> 5;
    int lane = threadIdx.x & 31;
    if (gw >= NNODES) return;
    const float4* xi = (const float4*)(x + (size_t)gw * DFEAT);
    float4 a0 = xi[lane], a1 = xi[lane + 32];
    float4 s0 = a0, s1 = a1;
    int e = roff[gw], end = roff[gw + 1];
    for (; e < end; ++e) {
        int   c = rnbr[e];
        float w = rw[e];
        const float4* xc = (const float4*)(x + (size_t)c * DFEAT);
        s0 = f4fma(s0, w, xc[lane]);
        s1 = f4fma(s1, w, xc[lane + 32]);
    }
    float4* Af = (float4*)(A + (size_t)gw * 1024);
    Af[128 + lane] = a0; Af[160 + lane] = a1;   // x     -> cols 512:768
    Af[192 + lane] = s0; Af[224 + lane] = s1;   // lap_x -> cols 768:1024
}

// ---------------- mean aggregation ----------------
__global__ void agg_kernel(const float* __restrict__ src, int sstride,
                           float* __restrict__ dst, int dstride,
                           const int* __restrict__ coff, const int* __restrict__ cnbr) {
    int gw   = (blockIdx.x * blockDim.x + threadIdx.x) >> 5;
    int lane = threadIdx.x & 31;
    if (gw >= NNODES) return;
    float4 a0 = f4z(), a1 = f4z(), a2 = f4z(), a3 = f4z();
    int beg = coff[gw], end = coff[gw + 1];
    for (int e = beg; e < end; ++e) {
        const float4* p = (const float4*)(src + (size_t)cnbr[e] * sstride);
        a0 = f4add(a0, p[lane]);
        a1 = f4add(a1, p[lane + 32]);
        a2 = f4add(a2, p[lane + 64]);
        a3 = f4add(a3, p[lane + 96]);
    }
    int cnt = end - beg;
    float sc = 1.f / (float)(cnt > 0 ? cnt : 1);
    float4* q = (float4*)(dst + (size_t)gw * dstride);
    q[lane]      = f4scale(a0, sc);
    q[lane + 32] = f4scale(a1, sc);
    q[lane + 64] = f4scale(a2, sc);
    q[lane + 96] = f4scale(a3, sc);
}

// ---------------- tensor-core GEMM (bf16 hi/lo split, fp32 accumulate) ----------------
// C[M,512] = A[M,1024] @ [Wl | Wr]^T + bias, optional exact GELU.
// Block tile 128x128, 8 warps (4m x 2n), warp tile 32x64, k-step 16.
template <bool GELU>
__global__ void __launch_bounds__(256) gemm_mma(
    const float* __restrict__ A,
    const float* __restrict__ Wl, const float* __restrict__ Wr,
    const float* __restrict__ bias,
    float* __restrict__ C) {
    // [buf][Ah,Al,Bh,Bl][row*8 + kkpair*2 + khalf] of packed bf16x2
    __shared__ unsigned sm[2][4][128 * 8];

    const int t    = threadIdx.x;
    const int bm   = blockIdx.y * 128, bn = blockIdx.x * 128;
    const int lane = t & 31, warp = t >> 5;
    const int wm   = warp & 3, wn = warp >> 2;
    const int g    = lane >> 2, tq = lane & 3;
    const int ar   = t >> 2, c4 = t & 3;

    float acc[2][8][4];
    #pragma unroll
    for (int i = 0; i < 2; ++i)
        #pragma unroll
        for (int j = 0; j < 8; ++j)
            #pragma unroll
            for (int q = 0; q < 4; ++q) acc[i][j][q] = 0.f;

    float4 ra0, ra1, rb0, rb1;

    const float* Abase0 = A + (size_t)(bm + ar) * 1024 + c4 * 4;
    const float* Abase1 = A + (size_t)(bm + ar + 64) * 1024 + c4 * 4;

    // gmem load of one k-step into registers
    auto load = [&](int k0) {
        ra0 = *(const float4*)(Abase0 + k0);
        ra1 = *(const float4*)(Abase1 + k0);
        const float* W = (k0 < 512) ? Wl : Wr;
        int kk = ((k0 < 512) ? k0 : k0 - 512) + c4 * 4;
        rb0 = *(const float4*)(W + (size_t)(bn + ar) * 512 + kk);
        rb1 = *(const float4*)(W + (size_t)(bn + ar + 64) * 512 + kk);
    };

    const int j0   = (c4 & 1) * 2;
    const int half = c4 >> 1;
    const int i00  = ar * 8 + j0 * 2 + half;
    const int i01  = ar * 8 + (j0 + 1) * 2 + half;

    auto store = [&](int buf) {
        unsigned* Ah = sm[buf][0]; unsigned* Al = sm[buf][1];
        unsigned* Bh = sm[buf][2]; unsigned* Bl = sm[buf][3];
        unsigned lo, hi;
        hi = pack_hi_lo(ra0.x, ra0.y, lo); Ah[i00] = hi;       Al[i00] = lo;
        hi = pack_hi_lo(ra0.z, ra0.w, lo); Ah[i01] = hi;       Al[i01] = lo;
        hi = pack_hi_lo(ra1.x, ra1.y, lo); Ah[i00 + 512] = hi; Al[i00 + 512] = lo;
        hi = pack_hi_lo(ra1.z, ra1.w, lo); Ah[i01 + 512] = hi; Al[i01 + 512] = lo;
        hi = pack_hi_lo(rb0.x, rb0.y, lo); Bh[i00] = hi;       Bl[i00] = lo;
        hi = pack_hi_lo(rb0.z, rb0.w, lo); Bh[i01] = hi;       Bl[i01] = lo;
        hi = pack_hi_lo(rb1.x, rb1.y, lo); Bh[i00 + 512] = hi; Bl[i00 + 512] = lo;
        hi = pack_hi_lo(rb1.z, rb1.w, lo); Bh[i01 + 512] = hi; Bl[i01 + 512] = lo;
    };

    auto compute = [&](int buf) {
        const uint2* Ah = (const uint2*)sm[buf][0];
        const uint2* Al = (const uint2*)sm[buf][1];
        const uint2* Bh = (const uint2*)sm[buf][2];
        const uint2* Bl = (const uint2*)sm[buf][3];
        uint2 bh[8], bl[8];
        #pragma unroll
        for (int nt = 0; nt < 8; ++nt) {
            int n = wn * 64 + nt * 8 + g;
            bh[nt] = Bh[n * 4 + tq];
            bl[nt] = Bl[n * 4 + tq];
        }
        #pragma unroll
        for (int mt = 0; mt < 2; ++mt) {
            int m = wm * 32 + mt * 16 + g;
            uint2 ah0 = Ah[m * 4 + tq], ah1 = Ah[(m + 8) * 4 + tq];
            uint2 al0 = Al[m * 4 + tq], al1 = Al[(m + 8) * 4 + tq];
            #pragma unroll
            for (int nt = 0; nt < 8; ++nt) {
                MMA_BF16(acc[mt][nt], ah0.x, ah1.x, ah0.y, ah1.y, bh[nt].x, bh[nt].y);
                MMA_BF16(acc[mt][nt], ah0.x, ah1.x, ah0.y, ah1.y, bl[nt].x, bl[nt].y);
                MMA_BF16(acc[mt][nt], al0.x, al1.x, al0.y, al1.y, bh[nt].x, bh[nt].y);
            }
        }
    };

    load(0);
    store(0);
    #pragma unroll 1
    for (int s = 0; s < 64; ++s) {
        __syncthreads();
        if (s < 63) load((s + 1) * 16);
        compute(s & 1);
        if (s < 63) store((s + 1) & 1);
    }

    #pragma unroll
    for (int mt = 0; mt < 2; ++mt) {
        int r0 = bm + wm * 32 + mt * 16 + g;
        #pragma unroll
        for (int nt = 0; nt < 8; ++nt) {
            int cc = bn + wn * 64 + nt * 8 + tq * 2;
            float b0v = bias[cc], b1v = bias[cc + 1];
            float v0 = acc[mt][nt][0] + b0v;
            float v1 = acc[mt][nt][1] + b1v;
            float v2 = acc[mt][nt][2] + b0v;
            float v3 = acc[mt][nt][3] + b1v;
            if (GELU) {
                v0 = 0.5f * v0 * (1.0f + erff(v0 * 0.70710678118654752f));
                v1 = 0.5f * v1 * (1.0f + erff(v1 * 0.70710678118654752f));
                v2 = 0.5f * v2 * (1.0f + erff(v2 * 0.70710678118654752f));
                v3 = 0.5f * v3 * (1.0f + erff(v3 * 0.70710678118654752f));
            }
            *(float2*)(C + (size_t)r0 * GD + cc)       = make_float2(v0, v1);
            *(float2*)(C + (size_t)(r0 + 8) * GD + cc) = make_float2(v2, v3);
        }
    }
}

// ---------------- pool: A2[g] = [ mean_s m2 , mean_s h ] ----------------
__global__ void pool_kernel(const float* __restrict__ m2, const float* __restrict__ h,
                            float* __restrict__ A2) {
    int g = blockIdx.x;
    int t = threadIdx.x;
    int c = t * 2;
    float2 sm = make_float2(0.f, 0.f), sh = make_float2(0.f, 0.f);
    const float* pm = m2 + (size_t)g * SNODES * GD + c;
    const float* ph = h  + (size_t)g * SNODES * GD + c;
    for (int s = 0; s < SNODES; ++s) {
        float2 vm = *(const float2*)(pm + (size_t)s * GD);
        float2 vh = *(const float2*)(ph + (size_t)s * GD);
        sm.x += vm.x; sm.y += vm.y;
        sh.x += vh.x; sh.y += vh.y;
    }
    const float inv = 1.0f / (float)SNODES;
    *(float2*)(A2 + (size_t)g * 1024 + c)       = make_float2(sm.x * inv, sm.y * inv);
    *(float2*)(A2 + (size_t)g * 1024 + 512 + c) = make_float2(sh.x * inv, sh.y * inv);
}

// ---------------- launcher ----------------
extern "C" void kernel_launch(void* const* d_in, const int* in_sizes, int n_in,
                              void* d_out, int out_size) {
    const float* x   = (const float*)d_in[0];
    const int*   ew  = (const int*)  d_in[1];
    const float* Wl1 = (const float*)d_in[2];
    const float* Wr1 = (const float*)d_in[3];
    const float* b1  = (const float*)d_in[4];
    const float* Wl2 = (const float*)d_in[5];
    const float* Wr2 = (const float*)d_in[6];
    const float* b2  = (const float*)d_in[7];
    int E = in_sizes[1] / 2;

    float *A, *h, *m2, *A2, *rw, *dinv;
    int *deg, *cnt, *roff, *coff, *curr, *curc, *rnbr, *cnbr, *bsum;
    cudaGetSymbolAddress((void**)&A,    g_A);
    cudaGetSymbolAddress((void**)&h,    g_h);
    cudaGetSymbolAddress((void**)&m2,   g_m2);
    cudaGetSymbolAddress((void**)&A2,   g_A2);
    cudaGetSymbolAddress((void**)&rw,   g_rw);
    cudaGetSymbolAddress((void**)&dinv, g_dinv);
    cudaGetSymbolAddress((void**)&deg,  g_deg);
    cudaGetSymbolAddress((void**)&cnt,  g_cnt);
    cudaGetSymbolAddress((void**)&roff, g_roff);
    cudaGetSymbolAddress((void**)&coff, g_coff);
    cudaGetSymbolAddress((void**)&curr, g_curr);
    cudaGetSymbolAddress((void**)&curc, g_curc);
    cudaGetSymbolAddress((void**)&rnbr, g_rnbr);
    cudaGetSymbolAddress((void**)&cnbr, g_cnbr);
    cudaGetSymbolAddress((void**)&bsum, g_bsum);

    int eb = (E + 255) / 256;

    init_kernel<<<(NNODES + 255) / 256, 256>>>(deg, cnt, curr, curc);
    detect_kernel<<<(2 * E + 255) / 256, 256>>>(ew, 2 * E);
    hist_kernel<<<eb, 256>>>(ew, E, deg, cnt);
    scan_p1<<<dim3(NBLK, 2), 256>>>(deg, cnt, bsum);
    scan_p2<<<1, 256>>>(bsum);
    scan_p3<<<dim3(NBLK, 2), 256>>>(deg, cnt, bsum, roff, coff);
    dinv_kernel<<<(NNODES + 255) / 256, 256>>>(deg, dinv);
    fill_kernel<<<eb, 256>>>(ew, E, dinv, roff, coff, curr, curc, rnbr, rw, cnbr);

    // lap + concat -> A[:,512:1024]
    lap_kernel<<<NNODES / 8, 256>>>(x, roff, rnbr, rw, A);
    // conv1 mean aggregation of x_comb -> A[:,0:512]
    agg_kernel<<<NNODES / 8, 256>>>(A + 512, 1024, A, 1024, coff, cnbr);
    // conv1 GEMM + bias + exact GELU -> h  (tensor cores, bf16 split)
    gemm_mma<true><<<dim3(4, NNODES / 128), 256>>>(A, Wl1, Wr1, b1, h);
    // conv2 mean aggregation of h -> m2
    agg_kernel<<<NNODES / 8, 256>>>(h, GD, m2, GD, coff, cnbr);
    // pool first (conv2 is linear): A2 = [pool(m2) | pool(h)]
    pool_kernel<<<NGRAPH, 256>>>(m2, h, A2);
    // conv2 GEMM + bias -> out [1024, 512]
    gemm_mma<false><<<dim3(4, NGRAPH / 128), 256>>>(A2, Wl2, Wr2, b2, (float*)d_out);
}